// round 10
// baseline (speedup 1.0000x reference)
#include <cuda_runtime.h>
#include <math.h>

#define N_NODES 4096
#define N_GRAPH 8
#define LOG2E   1.4426950408889634f
#define GSTRIDE 4194304   // int4 elements per graph (4096*4096/4)
#define KTOT    (N_NODES * 3)   // 12288
#define GAT_BLOCKS 296          // 2 per SM on 148 SMs
#define FC_CHUNKS 32
#define FC_OGROUPS 4
#define NOG 25                  // outputs per o-group
#define ROWS_PER_CHUNK (N_NODES / FC_CHUNKS)   // 128
#define KC (ROWS_PER_CHUNK * 3)                // 384

// Persistent scratch (no allocations allowed).
__device__ float4 g_table[N_NODES];           // swizzled: [(j&3)*1024 + (j>>2)] = (d'_j, Wh0, Wh1, Wh2)
__device__ float  g_sprime[N_NODES];          // s_i * log2(e)
__device__ float4 g_meanpart[64];             // per-prep-block sum of Wh (x,y,z used)
__device__ float4 g_part[N_NODES][2][N_GRAPH];// per-row partials: (sum, a0, a1, a2) per graph
__device__ float  g_fcpart[100 * N_GRAPH * FC_CHUNKS]; // [o][b][chunk] (chunk contiguous)
__device__ int    g_done = 0;                 // last-block counter (reset each run)

__device__ __forceinline__ float ex2f_fast(float x) {
    float r; asm("ex2.approx.ftz.f32 %0, %1;" : "=f"(r) : "f"(x)); return r;
}
__device__ __forceinline__ float maskf(int m, float w) {
    return __int_as_float((-m) & __float_as_int(w));
}
__device__ __forceinline__ float elu_fast(float x) {
    return x > 0.f ? x : ex2f_fast(x * LOG2E) - 1.0f;
}

// ---------------------------------------------------------------------------
// Kernel 1: Wh = emb @ W, s,d, swizzled table + per-block Wh sums (for mean).
// ---------------------------------------------------------------------------
__global__ void __launch_bounds__(256)
prep_kernel(const float* __restrict__ emb,
            const float* __restrict__ W,
            const float* __restrict__ a) {
    __shared__ float sW[384];
    __shared__ float sa[6];
    __shared__ float red[8][3];
    int tid = threadIdx.x;
    for (int k = tid; k < 384; k += 256) sW[k] = W[k];
    if (tid < 6) sa[tid] = a[tid];
    __syncthreads();

    int t  = blockIdx.x * 256 + tid;      // 0..16383
    int i  = t >> 2;                      // node
    int qd = t & 3;                       // quarter of the feature dim
    const float4* e4 = reinterpret_cast<const float4*>(emb + (size_t)i * 128) + qd * 8;
    float w0 = 0.f, w1 = 0.f, w2 = 0.f;
#pragma unroll
    for (int f4 = 0; f4 < 8; ++f4) {
        float4 e = e4[f4];
        int f = (qd * 8 + f4) * 4;
        w0 = fmaf(e.x, sW[(f+0)*3+0], w0); w1 = fmaf(e.x, sW[(f+0)*3+1], w1); w2 = fmaf(e.x, sW[(f+0)*3+2], w2);
        w0 = fmaf(e.y, sW[(f+1)*3+0], w0); w1 = fmaf(e.y, sW[(f+1)*3+1], w1); w2 = fmaf(e.y, sW[(f+1)*3+2], w2);
        w0 = fmaf(e.z, sW[(f+2)*3+0], w0); w1 = fmaf(e.z, sW[(f+2)*3+1], w1); w2 = fmaf(e.z, sW[(f+2)*3+2], w2);
        w0 = fmaf(e.w, sW[(f+3)*3+0], w0); w1 = fmaf(e.w, sW[(f+3)*3+1], w1); w2 = fmaf(e.w, sW[(f+3)*3+2], w2);
    }
#pragma unroll
    for (int off = 1; off <= 2; off <<= 1) {
        w0 += __shfl_xor_sync(0xffffffffu, w0, off);
        w1 += __shfl_xor_sync(0xffffffffu, w1, off);
        w2 += __shfl_xor_sync(0xffffffffu, w2, off);
    }
    if (qd == 0) {
        float s = w0*sa[0] + w1*sa[1] + w2*sa[2];
        float d = w0*sa[3] + w1*sa[4] + w2*sa[5];
        g_sprime[i] = s * LOG2E;
        g_table[(i & 3) * 1024 + (i >> 2)] = make_float4(d * LOG2E, w0, w1, w2);
    }
    // block-level Wh sum for mean fallback (each node counted 4x -> *0.25)
    float m0 = w0, m1 = w1, m2 = w2;
#pragma unroll
    for (int off = 4; off <= 16; off <<= 1) {
        m0 += __shfl_xor_sync(0xffffffffu, m0, off);
        m1 += __shfl_xor_sync(0xffffffffu, m1, off);
        m2 += __shfl_xor_sync(0xffffffffu, m2, off);
    }
    int lane = tid & 31, wp = tid >> 5;
    if (lane == 0) { red[wp][0] = m0; red[wp][1] = m1; red[wp][2] = m2; }
    __syncthreads();
    if (tid == 0) {
        float t0 = 0.f, t1 = 0.f, t2 = 0.f;
#pragma unroll
        for (int k = 0; k < 8; ++k) { t0 += red[k][0]; t1 += red[k][1]; t2 += red[k][2]; }
        g_meanpart[blockIdx.x] = make_float4(t0 * 0.25f, t1 * 0.25f, t2 * 0.25f, 0.f);
    }
}

// ---------------------------------------------------------------------------
// Kernel 2: fused GAT, exactly balanced quarter-row partition (unchanged).
// ---------------------------------------------------------------------------
__global__ void __launch_bounds__(256, 2)
gat8_kernel(const int* __restrict__ adj) {
    extern __shared__ float4 tbl[];   // 4096 float4 = 64 KB
    int tid = threadIdx.x;
    for (int idx = tid; idx < N_NODES; idx += 256)
        tbl[idx] = g_table[idx];
    __syncthreads();

    const float4* t0 = tbl;
    const float4* t1 = tbl + 1024;
    const float4* t2 = tbl + 2048;
    const float4* t3 = tbl + 3072;

    int lane = tid & 31;
    int w = blockIdx.x * 8 + (tid >> 5);          // 0..2367
    int qi = (w * 256 + 36) / 37;                 // quarter range [qi, qe)
    int qe = ((w + 1) * 256 + 36) / 37;

    const int4* adj4 = reinterpret_cast<const int4*>(adj);

    while (qi < qe) {
        int r = qi >> 2;
        int rowEnd = min(qe, (r + 1) << 2);
        int q0 = (qi - (r << 2)) << 8;            // start int4-index within row
        int q1 = (rowEnd - (r << 2)) << 8;        // end

        float sp = __ldg(&g_sprime[r]);
        const int4* arow = adj4 + (size_t)r * 1024;

        float sum[N_GRAPH], a0[N_GRAPH], a1[N_GRAPH], a2[N_GRAPH];
#pragma unroll
        for (int b = 0; b < N_GRAPH; ++b) { sum[b] = 0.f; a0[b] = 0.f; a1[b] = 0.f; a2[b] = 0.f; }

        for (int q = q0 + lane; q < q1; q += 32) {
            int4 m[N_GRAPH];
#pragma unroll
            for (int b = 0; b < N_GRAPH; ++b)
                m[b] = __ldcs(arow + (size_t)b * GSTRIDE + q);

            float4 gA = t0[q];
            float4 gB = t1[q];
            float4 gC = t2[q];
            float4 gD = t3[q];

            float xA = sp + gA.x; float wA = ex2f_fast(fmaxf(xA, 0.2f * xA));
            float xB = sp + gB.x; float wB = ex2f_fast(fmaxf(xB, 0.2f * xB));
            float xC = sp + gC.x; float wC = ex2f_fast(fmaxf(xC, 0.2f * xC));
            float xD = sp + gD.x; float wD = ex2f_fast(fmaxf(xD, 0.2f * xD));

#pragma unroll
            for (int b = 0; b < N_GRAPH; ++b) {
                float wx = maskf(m[b].x, wA);
                float wy = maskf(m[b].y, wB);
                float wz = maskf(m[b].z, wC);
                float ww = maskf(m[b].w, wD);
                sum[b] += (wx + wy) + (wz + ww);
                a0[b] = fmaf(wx, gA.y, a0[b]); a0[b] = fmaf(wy, gB.y, a0[b]);
                a0[b] = fmaf(wz, gC.y, a0[b]); a0[b] = fmaf(ww, gD.y, a0[b]);
                a1[b] = fmaf(wx, gA.z, a1[b]); a1[b] = fmaf(wy, gB.z, a1[b]);
                a1[b] = fmaf(wz, gC.z, a1[b]); a1[b] = fmaf(ww, gD.z, a1[b]);
                a2[b] = fmaf(wx, gA.w, a2[b]); a2[b] = fmaf(wy, gB.w, a2[b]);
                a2[b] = fmaf(wz, gC.w, a2[b]); a2[b] = fmaf(ww, gD.w, a2[b]);
            }
        }

#pragma unroll
        for (int b = 0; b < N_GRAPH; ++b) {
#pragma unroll
            for (int off = 16; off; off >>= 1) {
                sum[b] += __shfl_xor_sync(0xffffffffu, sum[b], off);
                a0[b]  += __shfl_xor_sync(0xffffffffu, a0[b],  off);
                a1[b]  += __shfl_xor_sync(0xffffffffu, a1[b],  off);
                a2[b]  += __shfl_xor_sync(0xffffffffu, a2[b],  off);
            }
        }

        if (lane == 0) {
            int slot = (q0 == 0) ? 0 : 1;
            float4* pp = &g_part[r][slot][0];
#pragma unroll
            for (int b = 0; b < N_GRAPH; ++b)
                pp[b] = make_float4(sum[b], a0[b], a1[b], a2[b]);
        }
        qi = rowEnd;
    }
}

// ---------------------------------------------------------------------------
// Kernel 3: per-(chunk, o-group): combine partials -> h (smem) -> GEMV.
// 128 blocks (chip-wide). Last block reduces chunk partials + bias -> out.
// ---------------------------------------------------------------------------
__global__ void __launch_bounds__(256)
fc_chunk_kernel(const float* __restrict__ fw, const float* __restrict__ fb,
                float* __restrict__ out) {
    __shared__ float hs[N_GRAPH][KC + 4];     // stride 388: conflict-free
    __shared__ float fbk[3];
    __shared__ int isLast;
    int c   = blockIdx.x;                     // 0..31 chunk
    int og  = blockIdx.y;                     // 0..3  o-group
    int tid = threadIdx.x;
    int lane = tid & 31, warp = tid >> 5;

    // Phase 0: fallback = elu(mean Wh) from the 64 prep partials (warp 0).
    if (warp == 0) {
        float4 v0 = g_meanpart[lane];
        float4 v1 = g_meanpart[lane + 32];
        float m0 = v0.x + v1.x, m1 = v0.y + v1.y, m2 = v0.z + v1.z;
#pragma unroll
        for (int off = 16; off; off >>= 1) {
            m0 += __shfl_xor_sync(0xffffffffu, m0, off);
            m1 += __shfl_xor_sync(0xffffffffu, m1, off);
            m2 += __shfl_xor_sync(0xffffffffu, m2, off);
        }
        if (lane == 0) {
            fbk[0] = elu_fast(m0 * (1.0f / N_NODES));
            fbk[1] = elu_fast(m1 * (1.0f / N_NODES));
            fbk[2] = elu_fast(m2 * (1.0f / N_NODES));
        }
    }
    __syncthreads();

    // Phase 1: combine + normalize + elu into smem. 1024 (row,b) pairs.
#pragma unroll
    for (int s = 0; s < 4; ++s) {
        int idx = s * 256 + tid;              // 0..1023
        int rl = idx >> 3;                    // local row 0..127
        int b  = idx & 7;
        int r  = c * ROWS_PER_CHUNK + rl;
        int w0 = ((r << 2) * 37) >> 8;
        int w3 = (((r << 2) + 3) * 37) >> 8;
        float4 p = g_part[r][0][b];
        if (w0 != w3) {
            float4 p1 = g_part[r][1][b];
            p.x += p1.x; p.y += p1.y; p.z += p1.z; p.w += p1.w;
        }
        float h0, h1, h2;
        if (p.x == 0.0f) {
            h0 = fbk[0]; h1 = fbk[1]; h2 = fbk[2];
        } else {
            float inv = 1.0f / p.x;
            h0 = elu_fast(p.y * inv);
            h1 = elu_fast(p.z * inv);
            h2 = elu_fast(p.w * inv);
        }
        hs[b][rl * 3 + 0] = h0;
        hs[b][rl * 3 + 1] = h1;
        hs[b][rl * 3 + 2] = h2;
    }
    __syncthreads();

    // Phase 2: warp-per-output GEMV over this chunk's 384-k slice,
    // outputs og*25 .. og*25+24.
    for (int oo = warp; oo < NOG; oo += 8) {
        int o = og * NOG + oo;
        const float* wrow = fw + (size_t)o * KTOT + c * KC;
        float acc[N_GRAPH];
#pragma unroll
        for (int b = 0; b < N_GRAPH; ++b) acc[b] = 0.f;
#pragma unroll
        for (int s = 0; s < 12; ++s) {        // 384 / 32
            int k = s * 32 + lane;
            float wv = __ldg(wrow + k);
#pragma unroll
            for (int b = 0; b < N_GRAPH; ++b)
                acc[b] = fmaf(wv, hs[b][k], acc[b]);
        }
#pragma unroll
        for (int b = 0; b < N_GRAPH; ++b)
#pragma unroll
            for (int off = 16; off; off >>= 1)
                acc[b] += __shfl_xor_sync(0xffffffffu, acc[b], off);
        if (lane == 0) {
#pragma unroll
            for (int b = 0; b < N_GRAPH; ++b)
                g_fcpart[((size_t)o * N_GRAPH + b) * FC_CHUNKS + c] = acc[b];
        }
    }

    // Phase 3: last block reduces all chunk partials + bias -> out.
    __threadfence();
    __syncthreads();
    if (tid == 0) {
        int v = atomicAdd(&g_done, 1);
        isLast = (v == FC_CHUNKS * FC_OGROUPS - 1) ? 1 : 0;
    }
    __syncthreads();
    if (isLast) {
        __threadfence();                      // acquire side
        for (int p = warp; p < 100 * N_GRAPH; p += 8) {  // p = o*8+b
            float v = g_fcpart[(size_t)p * FC_CHUNKS + lane];
#pragma unroll
            for (int off = 16; off; off >>= 1)
                v += __shfl_xor_sync(0xffffffffu, v, off);
            if (lane == 0) {
                int o = p >> 3, b = p & 7;
                out[b * 100 + o] = v + __ldg(&fb[o]);
            }
        }
        __syncthreads();
        if (tid == 0) g_done = 0;             // reset for next replay
    }
}

// ---------------------------------------------------------------------------
extern "C" void kernel_launch(void* const* d_in, const int* in_sizes, int n_in,
                              void* d_out, int out_size) {
    const int*   adj = (const int*)d_in[0];
    const float* emb = (const float*)d_in[1];
    const float* W   = (const float*)d_in[2];
    const float* a   = (const float*)d_in[3];
    const float* fw  = (const float*)d_in[4];
    const float* fb  = (const float*)d_in[5];
    float* out = (float*)d_out;

    cudaFuncSetAttribute(gat8_kernel, cudaFuncAttributeMaxDynamicSharedMemorySize, 65536);

    prep_kernel<<<64, 256>>>(emb, W, a);
    gat8_kernel<<<GAT_BLOCKS, 256, 65536>>>(adj);
    fc_chunk_kernel<<<dim3(FC_CHUNKS, FC_OGROUPS), 256>>>(fw, fb, out);
}

// round 11
// speedup vs baseline: 1.2938x; 1.2938x over previous
#include <cuda_runtime.h>
#include <math.h>

#define N_NODES 4096
#define N_GRAPH 8
#define LOG2E   1.4426950408889634f
#define GSTRIDE 4194304   // int4 elements per graph (4096*4096/4)
#define KTOT    (N_NODES * 3)   // 12288
#define KCHUNK  1536            // KTOT / 8
#define GAT_BLOCKS 296          // 2 per SM on 148 SMs
#define NWARPS   (GAT_BLOCKS * 8)   // 2368; 2368*256 == 37*16384 exactly

// Persistent scratch (no allocations allowed).
__device__ float4 g_table[N_NODES];           // swizzled: [(j&3)*1024 + (j>>2)] = (d'_j, Wh0, Wh1, Wh2)
__device__ float  g_sprime[N_NODES];          // s_i * log2(e)
__device__ float  g_fallback[3];              // elu(mean_j Wh_j) for all-masked rows
__device__ float4 g_part[N_NODES][2][N_GRAPH];// per-row partials: (sum, a0, a1, a2) per graph
__device__ float  g_h[N_GRAPH * KTOT];        // elu(attn @ Wh), [B][N*3]
__device__ float  g_fcpart[100 * N_GRAPH * 8];// [o][b][chunk] (chunk contiguous)

__device__ __forceinline__ float ex2f_fast(float x) {
    float r; asm("ex2.approx.ftz.f32 %0, %1;" : "=f"(r) : "f"(x)); return r;
}
__device__ __forceinline__ float maskf(int m, float w) {
    return __int_as_float((-m) & __float_as_int(w));
}
__device__ __forceinline__ float elu_fast(float x) {
    return x > 0.f ? x : ex2f_fast(x * LOG2E) - 1.0f;
}

// ---------------------------------------------------------------------------
// Kernel 1: Wh = emb @ W, s,d, build swizzled table. 8 lanes per node.
// ---------------------------------------------------------------------------
__global__ void __launch_bounds__(256)
prep_kernel(const float* __restrict__ emb,
            const float* __restrict__ W,
            const float* __restrict__ a) {
    __shared__ float sW[384];
    __shared__ float sa[6];
    int tid = threadIdx.x;
    for (int k = tid; k < 384; k += 256) sW[k] = W[k];
    if (tid < 6) sa[tid] = a[tid];
    __syncthreads();

    int t  = blockIdx.x * 256 + tid;      // 0..32767
    int i  = t >> 3;                      // node
    int ld = t & 7;                       // eighth of the feature dim
    const float4* e4 = reinterpret_cast<const float4*>(emb + (size_t)i * 128) + ld * 4;
    float w0 = 0.f, w1 = 0.f, w2 = 0.f;
#pragma unroll
    for (int f4 = 0; f4 < 4; ++f4) {
        float4 e = e4[f4];
        int f = (ld * 4 + f4) * 4;
        w0 = fmaf(e.x, sW[(f+0)*3+0], w0); w1 = fmaf(e.x, sW[(f+0)*3+1], w1); w2 = fmaf(e.x, sW[(f+0)*3+2], w2);
        w0 = fmaf(e.y, sW[(f+1)*3+0], w0); w1 = fmaf(e.y, sW[(f+1)*3+1], w1); w2 = fmaf(e.y, sW[(f+1)*3+2], w2);
        w0 = fmaf(e.z, sW[(f+2)*3+0], w0); w1 = fmaf(e.z, sW[(f+2)*3+1], w1); w2 = fmaf(e.z, sW[(f+2)*3+2], w2);
        w0 = fmaf(e.w, sW[(f+3)*3+0], w0); w1 = fmaf(e.w, sW[(f+3)*3+1], w1); w2 = fmaf(e.w, sW[(f+3)*3+2], w2);
    }
#pragma unroll
    for (int off = 1; off <= 4; off <<= 1) {
        w0 += __shfl_xor_sync(0xffffffffu, w0, off);
        w1 += __shfl_xor_sync(0xffffffffu, w1, off);
        w2 += __shfl_xor_sync(0xffffffffu, w2, off);
    }
    if (ld == 0) {
        float s = w0*sa[0] + w1*sa[1] + w2*sa[2];
        float d = w0*sa[3] + w1*sa[4] + w2*sa[5];
        g_sprime[i] = s * LOG2E;
        g_table[(i & 3) * 1024 + (i >> 2)] = make_float4(d * LOG2E, w0, w1, w2);
    }
}

// ---------------------------------------------------------------------------
// Kernel 2: fallback for all-masked rows: elu(mean_j Wh_j)
// ---------------------------------------------------------------------------
__global__ void __launch_bounds__(256)
mean_kernel() {
    int tid = threadIdx.x;
    float m0 = 0.f, m1 = 0.f, m2 = 0.f;
    for (int idx = tid; idx < N_NODES; idx += 256) {
        float4 g = g_table[idx];
        m0 += g.y; m1 += g.z; m2 += g.w;
    }
#pragma unroll
    for (int off = 16; off; off >>= 1) {
        m0 += __shfl_xor_sync(0xffffffffu, m0, off);
        m1 += __shfl_xor_sync(0xffffffffu, m1, off);
        m2 += __shfl_xor_sync(0xffffffffu, m2, off);
    }
    __shared__ float red[3][8];
    int lane = tid & 31, w = tid >> 5;
    if (lane == 0) { red[0][w] = m0; red[1][w] = m1; red[2][w] = m2; }
    __syncthreads();
    if (tid == 0) {
        float t0 = 0.f, t1 = 0.f, t2 = 0.f;
#pragma unroll
        for (int k = 0; k < 8; ++k) { t0 += red[0][k]; t1 += red[1][k]; t2 += red[2][k]; }
        t0 *= (1.0f / N_NODES); t1 *= (1.0f / N_NODES); t2 *= (1.0f / N_NODES);
        g_fallback[0] = t0 > 0.f ? t0 : expm1f(t0);
        g_fallback[1] = t1 > 0.f ? t1 : expm1f(t1);
        g_fallback[2] = t2 > 0.f ? t2 : expm1f(t2);
    }
}

// ---------------------------------------------------------------------------
// Kernel 3: fused GAT, exactly balanced. 16384 quarter-rows over 2368 warps
// (6-7 quarters each). Each row touched by <=2 warps; partials to fixed slots.
// ---------------------------------------------------------------------------
__global__ void __launch_bounds__(256, 2)
gat8_kernel(const int* __restrict__ adj) {
    extern __shared__ float4 tbl[];   // 4096 float4 = 64 KB
    int tid = threadIdx.x;
    for (int idx = tid; idx < N_NODES; idx += 256)
        tbl[idx] = g_table[idx];
    __syncthreads();

    const float4* t0 = tbl;
    const float4* t1 = tbl + 1024;
    const float4* t2 = tbl + 2048;
    const float4* t3 = tbl + 3072;

    int lane = tid & 31;
    int w = blockIdx.x * 8 + (tid >> 5);          // 0..2367
    int qi = (w * 256 + 36) / 37;                 // quarter range [qi, qe)
    int qe = ((w + 1) * 256 + 36) / 37;

    const int4* adj4 = reinterpret_cast<const int4*>(adj);

    while (qi < qe) {
        int r = qi >> 2;
        int rowEnd = min(qe, (r + 1) << 2);
        int q0 = (qi - (r << 2)) << 8;            // start int4-index within row
        int q1 = (rowEnd - (r << 2)) << 8;        // end

        float sp = __ldg(&g_sprime[r]);
        const int4* arow = adj4 + (size_t)r * 1024;

        float sum[N_GRAPH], a0[N_GRAPH], a1[N_GRAPH], a2[N_GRAPH];
#pragma unroll
        for (int b = 0; b < N_GRAPH; ++b) { sum[b] = 0.f; a0[b] = 0.f; a1[b] = 0.f; a2[b] = 0.f; }

        for (int q = q0 + lane; q < q1; q += 32) {
            int4 m[N_GRAPH];
#pragma unroll
            for (int b = 0; b < N_GRAPH; ++b)
                m[b] = __ldcs(arow + (size_t)b * GSTRIDE + q);

            float4 gA = t0[q];
            float4 gB = t1[q];
            float4 gC = t2[q];
            float4 gD = t3[q];

            float xA = sp + gA.x; float wA = ex2f_fast(fmaxf(xA, 0.2f * xA));
            float xB = sp + gB.x; float wB = ex2f_fast(fmaxf(xB, 0.2f * xB));
            float xC = sp + gC.x; float wC = ex2f_fast(fmaxf(xC, 0.2f * xC));
            float xD = sp + gD.x; float wD = ex2f_fast(fmaxf(xD, 0.2f * xD));

#pragma unroll
            for (int b = 0; b < N_GRAPH; ++b) {
                float wx = maskf(m[b].x, wA);
                float wy = maskf(m[b].y, wB);
                float wz = maskf(m[b].z, wC);
                float ww = maskf(m[b].w, wD);
                sum[b] += (wx + wy) + (wz + ww);
                a0[b] = fmaf(wx, gA.y, a0[b]); a0[b] = fmaf(wy, gB.y, a0[b]);
                a0[b] = fmaf(wz, gC.y, a0[b]); a0[b] = fmaf(ww, gD.y, a0[b]);
                a1[b] = fmaf(wx, gA.z, a1[b]); a1[b] = fmaf(wy, gB.z, a1[b]);
                a1[b] = fmaf(wz, gC.z, a1[b]); a1[b] = fmaf(ww, gD.z, a1[b]);
                a2[b] = fmaf(wx, gA.w, a2[b]); a2[b] = fmaf(wy, gB.w, a2[b]);
                a2[b] = fmaf(wz, gC.w, a2[b]); a2[b] = fmaf(ww, gD.w, a2[b]);
            }
        }

#pragma unroll
        for (int b = 0; b < N_GRAPH; ++b) {
#pragma unroll
            for (int off = 16; off; off >>= 1) {
                sum[b] += __shfl_xor_sync(0xffffffffu, sum[b], off);
                a0[b]  += __shfl_xor_sync(0xffffffffu, a0[b],  off);
                a1[b]  += __shfl_xor_sync(0xffffffffu, a1[b],  off);
                a2[b]  += __shfl_xor_sync(0xffffffffu, a2[b],  off);
            }
        }

        if (lane == 0) {
            int slot = (qi == (r << 2)) ? 0 : 1;  // own the row's first quarter?
            float4* pp = &g_part[r][slot][0];
#pragma unroll
            for (int b = 0; b < N_GRAPH; ++b)
                pp[b] = make_float4(sum[b], a0[b], a1[b], a2[b]);
        }
        qi = rowEnd;
    }
}

// ---------------------------------------------------------------------------
// Kernel 3b: combine partials, normalize, elu. One thread per (row, graph).
// ---------------------------------------------------------------------------
__global__ void __launch_bounds__(256)
combine_kernel() {
    int idx = blockIdx.x * 256 + threadIdx.x;     // 0..32767
    int r = idx >> 3;
    int b = idx & 7;
    int w0 = ((r << 2) * 37) >> 8;                // warp covering first quarter
    int w3 = (((r << 2) + 3) * 37) >> 8;          // warp covering last quarter
    float4 p = g_part[r][0][b];
    if (w0 != w3) {                               // row split across two warps
        float4 p1 = g_part[r][1][b];
        p.x += p1.x; p.y += p1.y; p.z += p1.z; p.w += p1.w;
    }
    float h0, h1, h2;
    if (p.x == 0.0f) {
        h0 = __ldg(&g_fallback[0]); h1 = __ldg(&g_fallback[1]); h2 = __ldg(&g_fallback[2]);
    } else {
        float inv = 1.0f / p.x;
        h0 = elu_fast(p.y * inv);
        h1 = elu_fast(p.z * inv);
        h2 = elu_fast(p.w * inv);
    }
    float* hp = g_h + (size_t)b * KTOT + (size_t)r * 3;
    hp[0] = h0; hp[1] = h1; hp[2] = h2;
}

// ---------------------------------------------------------------------------
// Kernel 4a: fc partials, 2 outputs per block (R6 best config).
// ---------------------------------------------------------------------------
__global__ void __launch_bounds__(128)
fc_part_kernel(const float* __restrict__ fw) {
    int o0 = blockIdx.x * 2;          // 0,2,..,98
    int c  = blockIdx.y;              // 0..7
    const float4* wA4 = reinterpret_cast<const float4*>(fw + (size_t)o0 * KTOT) + c * (KCHUNK / 4);
    const float4* wB4 = reinterpret_cast<const float4*>(fw + (size_t)(o0 + 1) * KTOT) + c * (KCHUNK / 4);

    float acc[2][N_GRAPH];
#pragma unroll
    for (int b = 0; b < N_GRAPH; ++b) { acc[0][b] = 0.f; acc[1][b] = 0.f; }

#pragma unroll
    for (int s = 0; s < 3; ++s) {                 // 384 float4 / 128 threads
        int kk = s * 128 + threadIdx.x;
        float4 wa = __ldg(wA4 + kk);
        float4 wb = __ldg(wB4 + kk);
#pragma unroll
        for (int b = 0; b < N_GRAPH; ++b) {
            const float4* gh4 = reinterpret_cast<const float4*>(g_h + (size_t)b * KTOT) + c * (KCHUNK / 4);
            float4 hv = gh4[kk];
            acc[0][b] = fmaf(wa.x, hv.x, acc[0][b]);
            acc[0][b] = fmaf(wa.y, hv.y, acc[0][b]);
            acc[0][b] = fmaf(wa.z, hv.z, acc[0][b]);
            acc[0][b] = fmaf(wa.w, hv.w, acc[0][b]);
            acc[1][b] = fmaf(wb.x, hv.x, acc[1][b]);
            acc[1][b] = fmaf(wb.y, hv.y, acc[1][b]);
            acc[1][b] = fmaf(wb.z, hv.z, acc[1][b]);
            acc[1][b] = fmaf(wb.w, hv.w, acc[1][b]);
        }
    }

#pragma unroll
    for (int oo = 0; oo < 2; ++oo)
#pragma unroll
        for (int b = 0; b < N_GRAPH; ++b)
#pragma unroll
            for (int off = 16; off; off >>= 1)
                acc[oo][b] += __shfl_xor_sync(0xffffffffu, acc[oo][b], off);

    __shared__ float red[4][16];
    int lane = threadIdx.x & 31, w = threadIdx.x >> 5;
    if (lane == 0) {
#pragma unroll
        for (int oo = 0; oo < 2; ++oo)
#pragma unroll
            for (int b = 0; b < N_GRAPH; ++b)
                red[w][oo * 8 + b] = acc[oo][b];
    }
    __syncthreads();
    if (threadIdx.x < 16) {
        int oo = threadIdx.x >> 3, b = threadIdx.x & 7;
        float v = red[0][threadIdx.x] + red[1][threadIdx.x] +
                  red[2][threadIdx.x] + red[3][threadIdx.x];
        // transposed layout: [o][b][chunk], chunk contiguous
        g_fcpart[(((size_t)(o0 + oo) * N_GRAPH) + b) * 8 + c] = v;
    }
}

// ---------------------------------------------------------------------------
// Kernel 4b: final sum over chunks + bias. 800 threads; 2 float4 loads each.
// ---------------------------------------------------------------------------
__global__ void __launch_bounds__(800)
fc_final_kernel(const float* __restrict__ fb, float* __restrict__ out) {
    int t = threadIdx.x;              // 0..799
    int b = t / 100;
    int o = t - b * 100;
    const float4* p4 = reinterpret_cast<const float4*>(g_fcpart + (((size_t)o * N_GRAPH) + b) * 8);
    float4 v0 = p4[0];
    float4 v1 = p4[1];
    out[b * 100 + o] = (v0.x + v0.y + v0.z + v0.w) +
                       (v1.x + v1.y + v1.z + v1.w) + fb[o];
}

// ---------------------------------------------------------------------------
extern "C" void kernel_launch(void* const* d_in, const int* in_sizes, int n_in,
                              void* d_out, int out_size) {
    const int*   adj = (const int*)d_in[0];
    const float* emb = (const float*)d_in[1];
    const float* W   = (const float*)d_in[2];
    const float* a   = (const float*)d_in[3];
    const float* fw  = (const float*)d_in[4];
    const float* fb  = (const float*)d_in[5];
    float* out = (float*)d_out;

    cudaFuncSetAttribute(gat8_kernel, cudaFuncAttributeMaxDynamicSharedMemorySize, 65536);

    prep_kernel<<<128, 256>>>(emb, W, a);
    mean_kernel<<<1, 256>>>();
    gat8_kernel<<<GAT_BLOCKS, 256, 65536>>>(adj);
    combine_kernel<<<128, 256>>>();
    fc_part_kernel<<<dim3(50, 8), 128>>>(fw);
    fc_final_kernel<<<1, 800>>>(fb, out);
}

// round 12
// speedup vs baseline: 1.3243x; 1.0236x over previous
#include <cuda_runtime.h>
#include <math.h>

#define N_NODES 4096
#define N_GRAPH 8
#define LOG2E   1.4426950408889634f
#define GSTRIDE 4194304   // int4 elements per graph (4096*4096/4)
#define KTOT    (N_NODES * 3)   // 12288
#define KCHUNK  1536            // KTOT / 8
#define GAT_BLOCKS 296          // 2 per SM on 148 SMs
#define PREP_BLOCKS 128

// Persistent scratch (no allocations allowed).
__device__ float4 g_table[N_NODES];           // swizzled: [(j&3)*1024 + (j>>2)] = (d'_j, Wh0, Wh1, Wh2)
__device__ float  g_sprime[N_NODES];          // s_i * log2(e)
__device__ float4 g_meanpart[PREP_BLOCKS];    // per-prep-block Wh sums (x,y,z)
__device__ float4 g_part[N_NODES][2][N_GRAPH];// per-row partials: (sum, a0, a1, a2) per graph
__device__ float  g_h[N_GRAPH * KTOT];        // elu(attn @ Wh), [B][N*3]
__device__ float  g_fcpart[100 * N_GRAPH * 8];// [o][b][chunk] (chunk contiguous)

__device__ __forceinline__ float ex2f_fast(float x) {
    float r; asm("ex2.approx.ftz.f32 %0, %1;" : "=f"(r) : "f"(x)); return r;
}
__device__ __forceinline__ float maskf(int m, float w) {
    return __int_as_float((-m) & __float_as_int(w));
}
__device__ __forceinline__ float elu_fast(float x) {
    return x > 0.f ? x : ex2f_fast(x * LOG2E) - 1.0f;
}

// ---------------------------------------------------------------------------
// Kernel 1: Wh = emb @ W, s,d, swizzled table + per-block Wh sums. 8 lanes/node.
// ---------------------------------------------------------------------------
__global__ void __launch_bounds__(256)
prep_kernel(const float* __restrict__ emb,
            const float* __restrict__ W,
            const float* __restrict__ a) {
    __shared__ float sW[384];
    __shared__ float sa[6];
    __shared__ float red[8][3];
    int tid = threadIdx.x;
    for (int k = tid; k < 384; k += 256) sW[k] = W[k];
    if (tid < 6) sa[tid] = a[tid];
    __syncthreads();

    int t  = blockIdx.x * 256 + tid;      // 0..32767
    int i  = t >> 3;                      // node
    int ld = t & 7;                       // eighth of the feature dim
    const float4* e4 = reinterpret_cast<const float4*>(emb + (size_t)i * 128) + ld * 4;
    float w0 = 0.f, w1 = 0.f, w2 = 0.f;
#pragma unroll
    for (int f4 = 0; f4 < 4; ++f4) {
        float4 e = e4[f4];
        int f = (ld * 4 + f4) * 4;
        w0 = fmaf(e.x, sW[(f+0)*3+0], w0); w1 = fmaf(e.x, sW[(f+0)*3+1], w1); w2 = fmaf(e.x, sW[(f+0)*3+2], w2);
        w0 = fmaf(e.y, sW[(f+1)*3+0], w0); w1 = fmaf(e.y, sW[(f+1)*3+1], w1); w2 = fmaf(e.y, sW[(f+1)*3+2], w2);
        w0 = fmaf(e.z, sW[(f+2)*3+0], w0); w1 = fmaf(e.z, sW[(f+2)*3+1], w1); w2 = fmaf(e.z, sW[(f+2)*3+2], w2);
        w0 = fmaf(e.w, sW[(f+3)*3+0], w0); w1 = fmaf(e.w, sW[(f+3)*3+1], w1); w2 = fmaf(e.w, sW[(f+3)*3+2], w2);
    }
#pragma unroll
    for (int off = 1; off <= 4; off <<= 1) {
        w0 += __shfl_xor_sync(0xffffffffu, w0, off);
        w1 += __shfl_xor_sync(0xffffffffu, w1, off);
        w2 += __shfl_xor_sync(0xffffffffu, w2, off);
    }
    if (ld == 0) {
        float s = w0*sa[0] + w1*sa[1] + w2*sa[2];
        float d = w0*sa[3] + w1*sa[4] + w2*sa[5];
        g_sprime[i] = s * LOG2E;
        g_table[(i & 3) * 1024 + (i >> 2)] = make_float4(d * LOG2E, w0, w1, w2);
    }
    // block Wh sum for the mean fallback (each node counted 8x -> *0.125)
    float m0 = w0, m1 = w1, m2 = w2;
#pragma unroll
    for (int off = 8; off <= 16; off <<= 1) {
        m0 += __shfl_xor_sync(0xffffffffu, m0, off);
        m1 += __shfl_xor_sync(0xffffffffu, m1, off);
        m2 += __shfl_xor_sync(0xffffffffu, m2, off);
    }
    int lane = tid & 31, wp = tid >> 5;
    if (lane == 0) { red[wp][0] = m0; red[wp][1] = m1; red[wp][2] = m2; }
    __syncthreads();
    if (tid == 0) {
        float t0 = 0.f, t1 = 0.f, t2 = 0.f;
#pragma unroll
        for (int k = 0; k < 8; ++k) { t0 += red[k][0]; t1 += red[k][1]; t2 += red[k][2]; }
        g_meanpart[blockIdx.x] = make_float4(t0 * 0.125f, t1 * 0.125f, t2 * 0.125f, 0.f);
    }
}

// ---------------------------------------------------------------------------
// Kernel 2: fused GAT, exactly balanced quarter-row partition (unchanged).
// ---------------------------------------------------------------------------
__global__ void __launch_bounds__(256, 2)
gat8_kernel(const int* __restrict__ adj) {
    extern __shared__ float4 tbl[];   // 4096 float4 = 64 KB
    int tid = threadIdx.x;
    for (int idx = tid; idx < N_NODES; idx += 256)
        tbl[idx] = g_table[idx];
    __syncthreads();

    const float4* t0 = tbl;
    const float4* t1 = tbl + 1024;
    const float4* t2 = tbl + 2048;
    const float4* t3 = tbl + 3072;

    int lane = tid & 31;
    int w = blockIdx.x * 8 + (tid >> 5);          // 0..2367
    int qi = (w * 256 + 36) / 37;                 // quarter range [qi, qe)
    int qe = ((w + 1) * 256 + 36) / 37;

    const int4* adj4 = reinterpret_cast<const int4*>(adj);

    while (qi < qe) {
        int r = qi >> 2;
        int rowEnd = min(qe, (r + 1) << 2);
        int q0 = (qi - (r << 2)) << 8;            // start int4-index within row
        int q1 = (rowEnd - (r << 2)) << 8;        // end

        float sp = __ldg(&g_sprime[r]);
        const int4* arow = adj4 + (size_t)r * 1024;

        float sum[N_GRAPH], a0[N_GRAPH], a1[N_GRAPH], a2[N_GRAPH];
#pragma unroll
        for (int b = 0; b < N_GRAPH; ++b) { sum[b] = 0.f; a0[b] = 0.f; a1[b] = 0.f; a2[b] = 0.f; }

        for (int q = q0 + lane; q < q1; q += 32) {
            int4 m[N_GRAPH];
#pragma unroll
            for (int b = 0; b < N_GRAPH; ++b)
                m[b] = __ldcs(arow + (size_t)b * GSTRIDE + q);

            float4 gA = t0[q];
            float4 gB = t1[q];
            float4 gC = t2[q];
            float4 gD = t3[q];

            float xA = sp + gA.x; float wA = ex2f_fast(fmaxf(xA, 0.2f * xA));
            float xB = sp + gB.x; float wB = ex2f_fast(fmaxf(xB, 0.2f * xB));
            float xC = sp + gC.x; float wC = ex2f_fast(fmaxf(xC, 0.2f * xC));
            float xD = sp + gD.x; float wD = ex2f_fast(fmaxf(xD, 0.2f * xD));

#pragma unroll
            for (int b = 0; b < N_GRAPH; ++b) {
                float wx = maskf(m[b].x, wA);
                float wy = maskf(m[b].y, wB);
                float wz = maskf(m[b].z, wC);
                float ww = maskf(m[b].w, wD);
                sum[b] += (wx + wy) + (wz + ww);
                a0[b] = fmaf(wx, gA.y, a0[b]); a0[b] = fmaf(wy, gB.y, a0[b]);
                a0[b] = fmaf(wz, gC.y, a0[b]); a0[b] = fmaf(ww, gD.y, a0[b]);
                a1[b] = fmaf(wx, gA.z, a1[b]); a1[b] = fmaf(wy, gB.z, a1[b]);
                a1[b] = fmaf(wz, gC.z, a1[b]); a1[b] = fmaf(ww, gD.z, a1[b]);
                a2[b] = fmaf(wx, gA.w, a2[b]); a2[b] = fmaf(wy, gB.w, a2[b]);
                a2[b] = fmaf(wz, gC.w, a2[b]); a2[b] = fmaf(ww, gD.w, a2[b]);
            }
        }

#pragma unroll
        for (int b = 0; b < N_GRAPH; ++b) {
#pragma unroll
            for (int off = 16; off; off >>= 1) {
                sum[b] += __shfl_xor_sync(0xffffffffu, sum[b], off);
                a0[b]  += __shfl_xor_sync(0xffffffffu, a0[b],  off);
                a1[b]  += __shfl_xor_sync(0xffffffffu, a1[b],  off);
                a2[b]  += __shfl_xor_sync(0xffffffffu, a2[b],  off);
            }
        }

        if (lane == 0) {
            int slot = (qi == (r << 2)) ? 0 : 1;  // own the row's first quarter?
            float4* pp = &g_part[r][slot][0];
#pragma unroll
            for (int b = 0; b < N_GRAPH; ++b)
                pp[b] = make_float4(sum[b], a0[b], a1[b], a2[b]);
        }
        qi = rowEnd;
    }
}

// ---------------------------------------------------------------------------
// Kernel 3: combine partials, normalize, elu; fallback computed from the
// prep mean-partials by warp 0 (absorbs the old mean kernel).
// ---------------------------------------------------------------------------
__global__ void __launch_bounds__(256)
combine_kernel() {
    __shared__ float fbk[3];
    int tid = threadIdx.x;
    int lane = tid & 31, warp = tid >> 5;

    if (warp == 0) {
        float4 v0 = g_meanpart[lane];
        float4 v1 = g_meanpart[lane + 32];
        float4 v2 = g_meanpart[lane + 64];
        float4 v3 = g_meanpart[lane + 96];
        float m0 = (v0.x + v1.x) + (v2.x + v3.x);
        float m1 = (v0.y + v1.y) + (v2.y + v3.y);
        float m2 = (v0.z + v1.z) + (v2.z + v3.z);
#pragma unroll
        for (int off = 16; off; off >>= 1) {
            m0 += __shfl_xor_sync(0xffffffffu, m0, off);
            m1 += __shfl_xor_sync(0xffffffffu, m1, off);
            m2 += __shfl_xor_sync(0xffffffffu, m2, off);
        }
        if (lane == 0) {
            fbk[0] = elu_fast(m0 * (1.0f / N_NODES));
            fbk[1] = elu_fast(m1 * (1.0f / N_NODES));
            fbk[2] = elu_fast(m2 * (1.0f / N_NODES));
        }
    }
    __syncthreads();

    int idx = blockIdx.x * 256 + tid;             // 0..32767
    int r = idx >> 3;
    int b = idx & 7;
    int w0 = ((r << 2) * 37) >> 8;                // warp covering first quarter
    int w3 = (((r << 2) + 3) * 37) >> 8;          // warp covering last quarter
    float4 p = g_part[r][0][b];
    if (w0 != w3) {                               // row split across two warps
        float4 p1 = g_part[r][1][b];
        p.x += p1.x; p.y += p1.y; p.z += p1.z; p.w += p1.w;
    }
    float h0, h1, h2;
    if (p.x == 0.0f) {
        h0 = fbk[0]; h1 = fbk[1]; h2 = fbk[2];
    } else {
        float inv = 1.0f / p.x;
        h0 = elu_fast(p.y * inv);
        h1 = elu_fast(p.z * inv);
        h2 = elu_fast(p.w * inv);
    }
    float* hp = g_h + (size_t)b * KTOT + (size_t)r * 3;
    hp[0] = h0; hp[1] = h1; hp[2] = h2;
}

// ---------------------------------------------------------------------------
// Kernel 4a: fc partials, 2 outputs per block (proven best config).
// ---------------------------------------------------------------------------
__global__ void __launch_bounds__(128)
fc_part_kernel(const float* __restrict__ fw) {
    int o0 = blockIdx.x * 2;          // 0,2,..,98
    int c  = blockIdx.y;              // 0..7
    const float4* wA4 = reinterpret_cast<const float4*>(fw + (size_t)o0 * KTOT) + c * (KCHUNK / 4);
    const float4* wB4 = reinterpret_cast<const float4*>(fw + (size_t)(o0 + 1) * KTOT) + c * (KCHUNK / 4);

    float acc[2][N_GRAPH];
#pragma unroll
    for (int b = 0; b < N_GRAPH; ++b) { acc[0][b] = 0.f; acc[1][b] = 0.f; }

#pragma unroll
    for (int s = 0; s < 3; ++s) {                 // 384 float4 / 128 threads
        int kk = s * 128 + threadIdx.x;
        float4 wa = __ldg(wA4 + kk);
        float4 wb = __ldg(wB4 + kk);
#pragma unroll
        for (int b = 0; b < N_GRAPH; ++b) {
            const float4* gh4 = reinterpret_cast<const float4*>(g_h + (size_t)b * KTOT) + c * (KCHUNK / 4);
            float4 hv = gh4[kk];
            acc[0][b] = fmaf(wa.x, hv.x, acc[0][b]);
            acc[0][b] = fmaf(wa.y, hv.y, acc[0][b]);
            acc[0][b] = fmaf(wa.z, hv.z, acc[0][b]);
            acc[0][b] = fmaf(wa.w, hv.w, acc[0][b]);
            acc[1][b] = fmaf(wb.x, hv.x, acc[1][b]);
            acc[1][b] = fmaf(wb.y, hv.y, acc[1][b]);
            acc[1][b] = fmaf(wb.z, hv.z, acc[1][b]);
            acc[1][b] = fmaf(wb.w, hv.w, acc[1][b]);
        }
    }

#pragma unroll
    for (int oo = 0; oo < 2; ++oo)
#pragma unroll
        for (int b = 0; b < N_GRAPH; ++b)
#pragma unroll
            for (int off = 16; off; off >>= 1)
                acc[oo][b] += __shfl_xor_sync(0xffffffffu, acc[oo][b], off);

    __shared__ float red[4][16];
    int lane = threadIdx.x & 31, w = threadIdx.x >> 5;
    if (lane == 0) {
#pragma unroll
        for (int oo = 0; oo < 2; ++oo)
#pragma unroll
            for (int b = 0; b < N_GRAPH; ++b)
                red[w][oo * 8 + b] = acc[oo][b];
    }
    __syncthreads();
    if (threadIdx.x < 16) {
        int oo = threadIdx.x >> 3, b = threadIdx.x & 7;
        float v = red[0][threadIdx.x] + red[1][threadIdx.x] +
                  red[2][threadIdx.x] + red[3][threadIdx.x];
        // transposed layout: [o][b][chunk], chunk contiguous
        g_fcpart[(((size_t)(o0 + oo) * N_GRAPH) + b) * 8 + c] = v;
    }
}

// ---------------------------------------------------------------------------
// Kernel 4b: final sum over chunks + bias. 800 threads; 2 float4 loads each.
// ---------------------------------------------------------------------------
__global__ void __launch_bounds__(800)
fc_final_kernel(const float* __restrict__ fb, float* __restrict__ out) {
    int t = threadIdx.x;              // 0..799
    int b = t / 100;
    int o = t - b * 100;
    const float4* p4 = reinterpret_cast<const float4*>(g_fcpart + (((size_t)o * N_GRAPH) + b) * 8);
    float4 v0 = p4[0];
    float4 v1 = p4[1];
    out[b * 100 + o] = (v0.x + v0.y + v0.z + v0.w) +
                       (v1.x + v1.y + v1.z + v1.w) + fb[o];
}

// ---------------------------------------------------------------------------
extern "C" void kernel_launch(void* const* d_in, const int* in_sizes, int n_in,
                              void* d_out, int out_size) {
    const int*   adj = (const int*)d_in[0];
    const float* emb = (const float*)d_in[1];
    const float* W   = (const float*)d_in[2];
    const float* a   = (const float*)d_in[3];
    const float* fw  = (const float*)d_in[4];
    const float* fb  = (const float*)d_in[5];
    float* out = (float*)d_out;

    cudaFuncSetAttribute(gat8_kernel, cudaFuncAttributeMaxDynamicSharedMemorySize, 65536);

    prep_kernel<<<PREP_BLOCKS, 256>>>(emb, W, a);
    gat8_kernel<<<GAT_BLOCKS, 256, 65536>>>(adj);
    combine_kernel<<<128, 256>>>();
    fc_part_kernel<<<dim3(50, 8), 128>>>(fw);
    fc_final_kernel<<<1, 800>>>(fb, out);
}

// round 13
// speedup vs baseline: 1.3433x; 1.0143x over previous
#include <cuda_runtime.h>
#include <math.h>

#define N_NODES 4096
#define N_GRAPH 8
#define LOG2E   1.4426950408889634f
#define GSTRIDE 4194304   // int4 elements per graph (4096*4096/4)
#define KTOT    (N_NODES * 3)   // 12288
#define KCHUNK  1536            // KTOT / 8
#define GAT_BLOCKS 296          // 2 per SM on 148 SMs
#define PREP_BLOCKS 128

// Persistent scratch (no allocations allowed).
__device__ float4 g_table[N_NODES];           // swizzled: [(j&3)*1024 + (j>>2)] = (d'_j, Wh0, Wh1, Wh2)
__device__ float  g_sprime[N_NODES];          // s_i * log2(e)
__device__ float4 g_meanpart[PREP_BLOCKS];    // per-prep-block Wh sums (x,y,z)
__device__ float4 g_part[N_NODES][2][N_GRAPH];// per-row partials: (sum, a0, a1, a2) per graph
__device__ float  g_h[N_GRAPH * KTOT];        // elu(attn @ Wh), [B][N*3]
__device__ float  g_fcpart[100 * N_GRAPH * 8];// [o][b][chunk] (chunk contiguous)

__device__ __forceinline__ float ex2f_fast(float x) {
    float r; asm("ex2.approx.ftz.f32 %0, %1;" : "=f"(r) : "f"(x)); return r;
}
__device__ __forceinline__ float maskf(int m, float w) {
    return __int_as_float((-m) & __float_as_int(w));
}
__device__ __forceinline__ float elu_fast(float x) {
    return x > 0.f ? x : ex2f_fast(x * LOG2E) - 1.0f;
}

// ---------------------------------------------------------------------------
// Kernel 1: Wh = emb @ W, s,d, swizzled table + per-block Wh sums. 8 lanes/node.
// ---------------------------------------------------------------------------
__global__ void __launch_bounds__(256)
prep_kernel(const float* __restrict__ emb,
            const float* __restrict__ W,
            const float* __restrict__ a) {
    __shared__ float sW[384];
    __shared__ float sa[6];
    __shared__ float red[8][3];
    int tid = threadIdx.x;
    for (int k = tid; k < 384; k += 256) sW[k] = W[k];
    if (tid < 6) sa[tid] = a[tid];
    __syncthreads();

    int t  = blockIdx.x * 256 + tid;      // 0..32767
    int i  = t >> 3;                      // node
    int ld = t & 7;                       // eighth of the feature dim
    const float4* e4 = reinterpret_cast<const float4*>(emb + (size_t)i * 128) + ld * 4;
    float w0 = 0.f, w1 = 0.f, w2 = 0.f;
#pragma unroll
    for (int f4 = 0; f4 < 4; ++f4) {
        float4 e = e4[f4];
        int f = (ld * 4 + f4) * 4;
        w0 = fmaf(e.x, sW[(f+0)*3+0], w0); w1 = fmaf(e.x, sW[(f+0)*3+1], w1); w2 = fmaf(e.x, sW[(f+0)*3+2], w2);
        w0 = fmaf(e.y, sW[(f+1)*3+0], w0); w1 = fmaf(e.y, sW[(f+1)*3+1], w1); w2 = fmaf(e.y, sW[(f+1)*3+2], w2);
        w0 = fmaf(e.z, sW[(f+2)*3+0], w0); w1 = fmaf(e.z, sW[(f+2)*3+1], w1); w2 = fmaf(e.z, sW[(f+2)*3+2], w2);
        w0 = fmaf(e.w, sW[(f+3)*3+0], w0); w1 = fmaf(e.w, sW[(f+3)*3+1], w1); w2 = fmaf(e.w, sW[(f+3)*3+2], w2);
    }
#pragma unroll
    for (int off = 1; off <= 4; off <<= 1) {
        w0 += __shfl_xor_sync(0xffffffffu, w0, off);
        w1 += __shfl_xor_sync(0xffffffffu, w1, off);
        w2 += __shfl_xor_sync(0xffffffffu, w2, off);
    }
    if (ld == 0) {
        float s = w0*sa[0] + w1*sa[1] + w2*sa[2];
        float d = w0*sa[3] + w1*sa[4] + w2*sa[5];
        g_sprime[i] = s * LOG2E;
        g_table[(i & 3) * 1024 + (i >> 2)] = make_float4(d * LOG2E, w0, w1, w2);
    }
    // block Wh sum for the mean fallback (each node counted 8x -> *0.125)
    float m0 = w0, m1 = w1, m2 = w2;
#pragma unroll
    for (int off = 8; off <= 16; off <<= 1) {
        m0 += __shfl_xor_sync(0xffffffffu, m0, off);
        m1 += __shfl_xor_sync(0xffffffffu, m1, off);
        m2 += __shfl_xor_sync(0xffffffffu, m2, off);
    }
    int lane = tid & 31, wp = tid >> 5;
    if (lane == 0) { red[wp][0] = m0; red[wp][1] = m1; red[wp][2] = m2; }
    __syncthreads();
    if (tid == 0) {
        float t0 = 0.f, t1 = 0.f, t2 = 0.f;
#pragma unroll
        for (int k = 0; k < 8; ++k) { t0 += red[k][0]; t1 += red[k][1]; t2 += red[k][2]; }
        g_meanpart[blockIdx.x] = make_float4(t0 * 0.125f, t1 * 0.125f, t2 * 0.125f, 0.f);
    }
}

// ---------------------------------------------------------------------------
// Kernel 2: fused GAT, exactly balanced quarter-row partition (unchanged).
// ---------------------------------------------------------------------------
__global__ void __launch_bounds__(256, 2)
gat8_kernel(const int* __restrict__ adj) {
    extern __shared__ float4 tbl[];   // 4096 float4 = 64 KB
    int tid = threadIdx.x;
    for (int idx = tid; idx < N_NODES; idx += 256)
        tbl[idx] = g_table[idx];
    __syncthreads();

    const float4* t0 = tbl;
    const float4* t1 = tbl + 1024;
    const float4* t2 = tbl + 2048;
    const float4* t3 = tbl + 3072;

    int lane = tid & 31;
    int w = blockIdx.x * 8 + (tid >> 5);          // 0..2367
    int qi = (w * 256 + 36) / 37;                 // quarter range [qi, qe)
    int qe = ((w + 1) * 256 + 36) / 37;

    const int4* adj4 = reinterpret_cast<const int4*>(adj);

    while (qi < qe) {
        int r = qi >> 2;
        int rowEnd = min(qe, (r + 1) << 2);
        int q0 = (qi - (r << 2)) << 8;            // start int4-index within row
        int q1 = (rowEnd - (r << 2)) << 8;        // end

        float sp = __ldg(&g_sprime[r]);
        const int4* arow = adj4 + (size_t)r * 1024;

        float sum[N_GRAPH], a0[N_GRAPH], a1[N_GRAPH], a2[N_GRAPH];
#pragma unroll
        for (int b = 0; b < N_GRAPH; ++b) { sum[b] = 0.f; a0[b] = 0.f; a1[b] = 0.f; a2[b] = 0.f; }

        for (int q = q0 + lane; q < q1; q += 32) {
            int4 m[N_GRAPH];
#pragma unroll
            for (int b = 0; b < N_GRAPH; ++b)
                m[b] = __ldcs(arow + (size_t)b * GSTRIDE + q);

            float4 gA = t0[q];
            float4 gB = t1[q];
            float4 gC = t2[q];
            float4 gD = t3[q];

            float xA = sp + gA.x; float wA = ex2f_fast(fmaxf(xA, 0.2f * xA));
            float xB = sp + gB.x; float wB = ex2f_fast(fmaxf(xB, 0.2f * xB));
            float xC = sp + gC.x; float wC = ex2f_fast(fmaxf(xC, 0.2f * xC));
            float xD = sp + gD.x; float wD = ex2f_fast(fmaxf(xD, 0.2f * xD));

#pragma unroll
            for (int b = 0; b < N_GRAPH; ++b) {
                float wx = maskf(m[b].x, wA);
                float wy = maskf(m[b].y, wB);
                float wz = maskf(m[b].z, wC);
                float ww = maskf(m[b].w, wD);
                sum[b] += (wx + wy) + (wz + ww);
                a0[b] = fmaf(wx, gA.y, a0[b]); a0[b] = fmaf(wy, gB.y, a0[b]);
                a0[b] = fmaf(wz, gC.y, a0[b]); a0[b] = fmaf(ww, gD.y, a0[b]);
                a1[b] = fmaf(wx, gA.z, a1[b]); a1[b] = fmaf(wy, gB.z, a1[b]);
                a1[b] = fmaf(wz, gC.z, a1[b]); a1[b] = fmaf(ww, gD.z, a1[b]);
                a2[b] = fmaf(wx, gA.w, a2[b]); a2[b] = fmaf(wy, gB.w, a2[b]);
                a2[b] = fmaf(wz, gC.w, a2[b]); a2[b] = fmaf(ww, gD.w, a2[b]);
            }
        }

#pragma unroll
        for (int b = 0; b < N_GRAPH; ++b) {
#pragma unroll
            for (int off = 16; off; off >>= 1) {
                sum[b] += __shfl_xor_sync(0xffffffffu, sum[b], off);
                a0[b]  += __shfl_xor_sync(0xffffffffu, a0[b],  off);
                a1[b]  += __shfl_xor_sync(0xffffffffu, a1[b],  off);
                a2[b]  += __shfl_xor_sync(0xffffffffu, a2[b],  off);
            }
        }

        if (lane == 0) {
            int slot = (qi == (r << 2)) ? 0 : 1;  // own the row's first quarter?
            float4* pp = &g_part[r][slot][0];
#pragma unroll
            for (int b = 0; b < N_GRAPH; ++b)
                pp[b] = make_float4(sum[b], a0[b], a1[b], a2[b]);
        }
        qi = rowEnd;
    }
}

// ---------------------------------------------------------------------------
// Kernel 3: combine partials, normalize, elu; fallback computed from the
// prep mean-partials by warp 0 (absorbs the old mean kernel).
// ---------------------------------------------------------------------------
__global__ void __launch_bounds__(256)
combine_kernel() {
    __shared__ float fbk[3];
    int tid = threadIdx.x;
    int lane = tid & 31, warp = tid >> 5;

    if (warp == 0) {
        float4 v0 = g_meanpart[lane];
        float4 v1 = g_meanpart[lane + 32];
        float4 v2 = g_meanpart[lane + 64];
        float4 v3 = g_meanpart[lane + 96];
        float m0 = (v0.x + v1.x) + (v2.x + v3.x);
        float m1 = (v0.y + v1.y) + (v2.y + v3.y);
        float m2 = (v0.z + v1.z) + (v2.z + v3.z);
#pragma unroll
        for (int off = 16; off; off >>= 1) {
            m0 += __shfl_xor_sync(0xffffffffu, m0, off);
            m1 += __shfl_xor_sync(0xffffffffu, m1, off);
            m2 += __shfl_xor_sync(0xffffffffu, m2, off);
        }
        if (lane == 0) {
            fbk[0] = elu_fast(m0 * (1.0f / N_NODES));
            fbk[1] = elu_fast(m1 * (1.0f / N_NODES));
            fbk[2] = elu_fast(m2 * (1.0f / N_NODES));
        }
    }
    __syncthreads();

    int idx = blockIdx.x * 256 + tid;             // 0..32767
    int r = idx >> 3;
    int b = idx & 7;
    int w0 = ((r << 2) * 37) >> 8;                // warp covering first quarter
    int w3 = (((r << 2) + 3) * 37) >> 8;          // warp covering last quarter
    float4 p = g_part[r][0][b];
    if (w0 != w3) {                               // row split across two warps
        float4 p1 = g_part[r][1][b];
        p.x += p1.x; p.y += p1.y; p.z += p1.z; p.w += p1.w;
    }
    float h0, h1, h2;
    if (p.x == 0.0f) {
        h0 = fbk[0]; h1 = fbk[1]; h2 = fbk[2];
    } else {
        float inv = 1.0f / p.x;
        h0 = elu_fast(p.y * inv);
        h1 = elu_fast(p.z * inv);
        h2 = elu_fast(p.w * inv);
    }
    float* hp = g_h + (size_t)b * KTOT + (size_t)r * 3;
    hp[0] = h0; hp[1] = h1; hp[2] = h2;
}

// ---------------------------------------------------------------------------
// Kernel 4a: fc partials, 2 outputs per block (proven best config).
// ---------------------------------------------------------------------------
__global__ void __launch_bounds__(128)
fc_part_kernel(const float* __restrict__ fw) {
    int o0 = blockIdx.x * 2;          // 0,2,..,98
    int c  = blockIdx.y;              // 0..7
    const float4* wA4 = reinterpret_cast<const float4*>(fw + (size_t)o0 * KTOT) + c * (KCHUNK / 4);
    const float4* wB4 = reinterpret_cast<const float4*>(fw + (size_t)(o0 + 1) * KTOT) + c * (KCHUNK / 4);

    float acc[2][N_GRAPH];
#pragma unroll
    for (int b = 0; b < N_GRAPH; ++b) { acc[0][b] = 0.f; acc[1][b] = 0.f; }

#pragma unroll
    for (int s = 0; s < 3; ++s) {                 // 384 float4 / 128 threads
        int kk = s * 128 + threadIdx.x;
        float4 wa = __ldg(wA4 + kk);
        float4 wb = __ldg(wB4 + kk);
#pragma unroll
        for (int b = 0; b < N_GRAPH; ++b) {
            const float4* gh4 = reinterpret_cast<const float4*>(g_h + (size_t)b * KTOT) + c * (KCHUNK / 4);
            float4 hv = gh4[kk];
            acc[0][b] = fmaf(wa.x, hv.x, acc[0][b]);
            acc[0][b] = fmaf(wa.y, hv.y, acc[0][b]);
            acc[0][b] = fmaf(wa.z, hv.z, acc[0][b]);
            acc[0][b] = fmaf(wa.w, hv.w, acc[0][b]);
            acc[1][b] = fmaf(wb.x, hv.x, acc[1][b]);
            acc[1][b] = fmaf(wb.y, hv.y, acc[1][b]);
            acc[1][b] = fmaf(wb.z, hv.z, acc[1][b]);
            acc[1][b] = fmaf(wb.w, hv.w, acc[1][b]);
        }
    }

#pragma unroll
    for (int oo = 0; oo < 2; ++oo)
#pragma unroll
        for (int b = 0; b < N_GRAPH; ++b)
#pragma unroll
            for (int off = 16; off; off >>= 1)
                acc[oo][b] += __shfl_xor_sync(0xffffffffu, acc[oo][b], off);

    __shared__ float red[4][16];
    int lane = threadIdx.x & 31, w = threadIdx.x >> 5;
    if (lane == 0) {
#pragma unroll
        for (int oo = 0; oo < 2; ++oo)
#pragma unroll
            for (int b = 0; b < N_GRAPH; ++b)
                red[w][oo * 8 + b] = acc[oo][b];
    }
    __syncthreads();
    if (threadIdx.x < 16) {
        int oo = threadIdx.x >> 3, b = threadIdx.x & 7;
        float v = red[0][threadIdx.x] + red[1][threadIdx.x] +
                  red[2][threadIdx.x] + red[3][threadIdx.x];
        // transposed layout: [o][b][chunk], chunk contiguous
        g_fcpart[(((size_t)(o0 + oo) * N_GRAPH) + b) * 8 + c] = v;
    }
}

// ---------------------------------------------------------------------------
// Kernel 4b: final sum over chunks + bias. 800 threads; 2 float4 loads each.
// ---------------------------------------------------------------------------
__global__ void __launch_bounds__(800)
fc_final_kernel(const float* __restrict__ fb, float* __restrict__ out) {
    int t = threadIdx.x;              // 0..799
    int b = t / 100;
    int o = t - b * 100;
    const float4* p4 = reinterpret_cast<const float4*>(g_fcpart + (((size_t)o * N_GRAPH) + b) * 8);
    float4 v0 = p4[0];
    float4 v1 = p4[1];
    out[b * 100 + o] = (v0.x + v0.y + v0.z + v0.w) +
                       (v1.x + v1.y + v1.z + v1.w) + fb[o];
}

// ---------------------------------------------------------------------------
extern "C" void kernel_launch(void* const* d_in, const int* in_sizes, int n_in,
                              void* d_out, int out_size) {
    const int*   adj = (const int*)d_in[0];
    const float* emb = (const float*)d_in[1];
    const float* W   = (const float*)d_in[2];
    const float* a   = (const float*)d_in[3];
    const float* fw  = (const float*)d_in[4];
    const float* fb  = (const float*)d_in[5];
    float* out = (float*)d_out;

    cudaFuncSetAttribute(gat8_kernel, cudaFuncAttributeMaxDynamicSharedMemorySize, 65536);

    prep_kernel<<<PREP_BLOCKS, 256>>>(emb, W, a);
    gat8_kernel<<<GAT_BLOCKS, 256, 65536>>>(adj);
    combine_kernel<<<128, 256>>>();
    fc_part_kernel<<<dim3(50, 8), 128>>>(fw);
    fc_final_kernel<<<1, 800>>>(fb, out);
}